// round 14
// baseline (speedup 1.0000x reference)
#include <cuda_runtime.h>
#include <math.h>

#define Bv   2
#define Nv   4096
#define CIN  64
#define COUT 128
#define KNB  24
#define R2   0.0225f

// Output layout: pc (2*4096*6) | fout (2*128*4096) | pe (2*128*4096*24)
#define PC_ELEMS   (Bv*Nv*6)
#define FOUT_OFF   (PC_ELEMS)
#define FOUT_ELEMS (Bv*COUT*Nv)
#define PE_OFF     (FOUT_OFF + FOUT_ELEMS)

#define NSEG   (Bv*Nv)            // 8192 flat segments of 72 floats
#define DPLEN  (Bv*3*Nv*KNB)      // 589824

__device__ float g_f1t[Bv*Nv*COUT];   // transposed  [b][n][c]
__device__ float g_dp[DPLEN];
__device__ float g_ndp[DPLEN];
__device__ float g_nn[DPLEN];
__device__ int   g_idx[Bv*Nv*KNB];
__device__ int   g_jsel[NSEG*KNB];

__device__ __forceinline__ unsigned f2tf(float x) {
    unsigned r; asm("cvt.rna.tf32.f32 %0, %1;" : "=r"(r) : "f"(x)); return r;
}
__device__ __forceinline__ void mma_tf32(float* d, unsigned a0, unsigned a1, unsigned a2, unsigned a3,
                                         unsigned b0, unsigned b1) {
    asm volatile(
        "mma.sync.aligned.m16n8k8.row.col.f32.tf32.tf32.f32 "
        "{%0,%1,%2,%3}, {%4,%5,%6,%7}, {%8,%9}, {%0,%1,%2,%3};\n"
        : "+f"(d[0]), "+f"(d[1]), "+f"(d[2]), "+f"(d[3])
        : "r"(a0), "r"(a1), "r"(a2), "r"(a3), "r"(b0), "r"(b1));
}

// k_final dynamic smem layout (persistent fragment-packed ww)
//   aw   : uint4[8 R][16 ks][32 lane] = 65536 B  (persistent A-fragments)
//   fj2t : unsigned[48][132]          = 25344 B  (per pair tf32 fj2)
//   A-region (union): cols[24][128] f32 (12288) / lgt[128][25] f32 (12800)
#define SM_AW    0
#define SM_FJ2T  65536
#define SM_A     (SM_FJ2T + 48*132*4)           // 90880
#define SM_TOTAL (SM_A + 12800)                 // 103680
#define NPAIRS   (Bv*Nv/2)                      // 4096
#define FINAL_GRID 296                          // 148 SMs x 2 blocks

// ---------------------------------------------------------------- f1 = relu(bn(w1 @ f)); store transposed [b][n][c]
__global__ void k_f1(const float* __restrict__ f, const float* __restrict__ w1,
                     const float* __restrict__ g1, const float* __restrict__ b1) {
    int b = blockIdx.y;
    int col0 = blockIdx.x * 32;
    int t = threadIdx.x; // 128 threads = out channel
    __shared__ float fs[64][32];
    for (int e = t; e < 64 * 32; e += 128) {
        int row = e >> 5, col = e & 31;
        fs[row][col] = f[((size_t)b * CIN + row) * Nv + col0 + col];
    }
    __syncthreads();
    float acc[32];
#pragma unroll
    for (int i = 0; i < 32; i++) acc[i] = 0.f;
    const float* wr = w1 + t * CIN;
    for (int ci = 0; ci < CIN; ci++) {
        float wv = __ldg(wr + ci);
        const float4* r = (const float4*)&fs[ci][0];
#pragma unroll
        for (int q = 0; q < 8; q++) {
            float4 v = r[q];
            acc[4*q+0] = fmaf(wv, v.x, acc[4*q+0]);
            acc[4*q+1] = fmaf(wv, v.y, acc[4*q+1]);
            acc[4*q+2] = fmaf(wv, v.z, acc[4*q+2]);
            acc[4*q+3] = fmaf(wv, v.w, acc[4*q+3]);
        }
    }
    float inv = rsqrtf(1.0f + 1e-5f);
    float s = g1[t] * inv, bb = b1[t];
    float* ot = g_f1t + ((size_t)b * Nv + col0) * COUT + t;
#pragma unroll
    for (int i = 0; i < 32; i++)
        ot[(size_t)i * COUT] = fmaxf(fmaf(acc[i], s, bb), 0.f);
}

// ---------------------------------------------------------------- ball query 1: 32 queries/block; pc copy folded
__global__ __launch_bounds__(1024) void k_ballq(const float* __restrict__ pc, float* __restrict__ out) {
    __shared__ float sx[2048], sy[2048], sz[2048];
    __shared__ int   widx[32][KNB];
    __shared__ float sdp[32][3][KNB];
    int b = blockIdx.y;
    int t = threadIdx.x; // 1024
    int w = t >> 5, lane = t & 31;
    int n = blockIdx.x * 32 + w;
    const float* qp = pc + ((size_t)b * Nv + n) * 6;
    float qx = qp[0], qy = qp[1], qz = qp[2];
    float qq = qx*qx + qy*qy + qz*qz;
    int count = 0;
    for (int c = 0; c < 2; c++) {
        __syncthreads();
        for (int i = t; i < 2048; i += 1024) {
            const float* pp = pc + ((size_t)b * Nv + c * 2048 + i) * 6;
            sx[i] = pp[0]; sy[i] = pp[1]; sz[i] = pp[2];
        }
        __syncthreads();
        if (count >= KNB) continue;
        for (int base = 0; base < 2048; base += 32) {
            int s = base + lane;
            float x = sx[s], y = sy[s], z = sz[s];
            float ss = x*x + y*y + z*z;
            float d2 = qq + ss - 2.f * (qx*x + qy*y + qz*z);
            bool hit = d2 < R2;
            unsigned m = __ballot_sync(0xffffffffu, hit);
            if (hit) {
                int r = count + __popc(m & ((1u << lane) - 1u));
                if (r < KNB) {
                    widx[w][r] = c * 2048 + s;
                    sdp[w][0][r] = x - qx;
                    sdp[w][1][r] = y - qy;
                    sdp[w][2][r] = z - qz;
                }
            }
            count += __popc(m);
            if (count >= KNB) break;
        }
    }
    __syncwarp();
    int cnt = count > KNB ? KNB : count;
    if (lane < KNB) {
        int src = (lane < cnt) ? lane : 0;
        size_t gi = ((size_t)b * Nv + n) * KNB + lane;
        g_idx[gi] = widx[w][src];
        g_dp[(((size_t)b*3 + 0) * Nv + n) * KNB + lane] = sdp[w][0][src];
        g_dp[(((size_t)b*3 + 1) * Nv + n) * KNB + lane] = sdp[w][1][src];
        g_dp[(((size_t)b*3 + 2) * Nv + n) * KNB + lane] = sdp[w][2][src];
    }
    if (blockIdx.x == 0) {
        const float* src = pc + (size_t)b * Nv * 6;
        float* dst = out + (size_t)b * Nv * 6;
        for (int i = t; i < Nv * 6; i += 1024) dst[i] = src[i];
    }
}

// ---------------------------------------------------------------- FPS on flat 72-float segments (REDUX argmax)
__global__ void k_fps() {
    int t = threadIdx.x, w = t >> 5, lane = t & 31;
    int g = blockIdx.x * 8 + w;
    __shared__ float sp[8][KNB][3];
    __shared__ int   sperm[8][KNB];
    const float* seg = g_dp + (size_t)g * 72;
    if (lane < KNB) {
        sp[w][lane][0] = seg[lane*3];
        sp[w][lane][1] = seg[lane*3+1];
        sp[w][lane][2] = seg[lane*3+2];
    }
    __syncwarp();
    float px = 0.f, py = 0.f, pz = 0.f, dist = 1e10f;
    if (lane < KNB) { px = sp[w][lane][0]; py = sp[w][lane][1]; pz = sp[w][lane][2]; }
    int last = 0;
    if (lane == 0) sperm[w][0] = 0;
    for (int i = 1; i < KNB; i++) {
        float lx = __shfl_sync(0xffffffffu, px, last);
        float ly = __shfl_sync(0xffffffffu, py, last);
        float lz = __shfl_sync(0xffffffffu, pz, last);
        float dx = px - lx, dy = py - ly, dz = pz - lz;
        float d = dx*dx + dy*dy + dz*dz;
        if (lane < KNB) dist = fminf(dist, d);
        unsigned key = (lane < KNB) ? __float_as_uint(dist) : 0u;
        unsigned mv = __reduce_max_sync(0xffffffffu, key);
        unsigned elig = __ballot_sync(0xffffffffu, key == mv);
        last = __ffs(elig) - 1;
        if (lane == 0) sperm[w][i] = last;
    }
    __syncwarp();
    float* o = g_ndp + (size_t)g * 72;
    if (lane < KNB) {
        int s = sperm[w][lane];
        o[lane*3]   = sp[w][s][0];
        o[lane*3+1] = sp[w][s][1];
        o[lane*3+2] = sp[w][s][2];
    }
}

// ---------------------------------------------------------------- delta MLP (3->32->16->3); block (24,8): k=tx, no divides
__global__ __launch_bounds__(192) void k_mlp(
    const float* __restrict__ wd1, const float* __restrict__ gd1, const float* __restrict__ bd1,
    const float* __restrict__ wd2, const float* __restrict__ gd2, const float* __restrict__ bd2,
    const float* __restrict__ wd3, const float* __restrict__ gd3, const float* __restrict__ bd3) {
    __shared__ float s_wd1[96], s_a1[32], s_b1[32];
    __shared__ float s_wd2[512], s_a2[16], s_b2[16];
    __shared__ float s_wd3[48], s_a3[3], s_b3[3];
    int tid = threadIdx.y * 24 + threadIdx.x; // 192
    float inv = rsqrtf(1.0f + 1e-5f);
    if (tid < 96) s_wd1[tid] = wd1[tid];
    if (tid < 32) { s_a1[tid] = gd1[tid] * inv; s_b1[tid] = bd1[tid]; }
    for (int i = tid; i < 512; i += 192) s_wd2[i] = wd2[i];
    if (tid < 16) { s_a2[tid] = gd2[tid] * inv; s_b2[tid] = bd2[tid]; }
    if (tid >= 96 && tid < 144) s_wd3[tid-96] = wd3[tid-96];
    if (tid >= 144 && tid < 147) { s_a3[tid-144] = gd3[tid-144] * inv; s_b3[tid-144] = bd3[tid-144]; }
    __syncthreads();
    int k = threadIdx.x;                       // 0..23
    int n = blockIdx.x * 8 + threadIdx.y;      // 0..4095
    int b = blockIdx.y;
    size_t base = (((size_t)b * 3) * Nv + n) * KNB + k;
    const size_t CS = (size_t)Nv * KNB;
    float x0 = g_ndp[base], x1 = g_ndp[base + CS], x2 = g_ndp[base + 2*CS];
    float h2[16];
#pragma unroll
    for (int o = 0; o < 16; o++) h2[o] = 0.f;
#pragma unroll
    for (int c1 = 0; c1 < 32; c1++) {
        float a = s_wd1[c1*3]*x0 + s_wd1[c1*3+1]*x1 + s_wd1[c1*3+2]*x2;
        float h1v = fmaxf(fmaf(a, s_a1[c1], s_b1[c1]), 0.f);
#pragma unroll
        for (int o = 0; o < 16; o++)
            h2[o] = fmaf(s_wd2[o*32+c1], h1v, h2[o]);
    }
#pragma unroll
    for (int o = 0; o < 16; o++)
        h2[o] = fmaxf(fmaf(h2[o], s_a2[o], s_b2[o]), 0.f);
#pragma unroll
    for (int c = 0; c < 3; c++) {
        float a = 0.f;
#pragma unroll
        for (int ci = 0; ci < 16; ci++) a = fmaf(s_wd3[c*16+ci], h2[ci], a);
        float d = fmaf(a, s_a3[c], s_b3[c]);
        float xin = (c == 0) ? x0 : (c == 1) ? x1 : x2;
        g_ndp[base + (size_t)c * CS] = xin + d;
    }
}

// ---------------------------------------------------------------- NN query (k=1) on flat segments: q=new_dp, s=dp
__global__ void k_nnq() {
    int t = threadIdx.x, w = t >> 5, lane = t & 31;
    int g = blockIdx.x * 8 + w;
    __shared__ float sp[8][KNB][3];
    __shared__ float sss[8][KNB];
    const float* sseg = g_dp + (size_t)g * 72;
    if (lane < KNB) {
        float x = sseg[lane*3], y = sseg[lane*3+1], z = sseg[lane*3+2];
        sp[w][lane][0] = x; sp[w][lane][1] = y; sp[w][lane][2] = z;
        sss[w][lane] = x*x + y*y + z*z;
    }
    __syncwarp();
    if (lane < KNB) {
        const float* qseg = g_ndp + (size_t)g * 72;
        float qx = qseg[lane*3], qy = qseg[lane*3+1], qz = qseg[lane*3+2];
        float qq = qx*qx + qy*qy + qz*qz;
        int found = -1;
        for (int jj = 0; jj < KNB; jj++) {
            float d2 = qq + sss[w][jj] - 2.f * (qx*sp[w][jj][0] + qy*sp[w][jj][1] + qz*sp[w][jj][2]);
            if (d2 < R2) { found = jj; break; }
        }
        int j = found < 0 ? 0 : found;
        g_jsel[g * KNB + lane] = j;
        float* o = g_nn + (size_t)g * 72;
        o[0*KNB + lane] = sp[w][j][0] - qx;
        o[1*KNB + lane] = sp[w][j][1] - qy;
        o[2*KNB + lane] = sp[w][j][2] - qz;
    }
}

// ---------------------------------------------------------------- fused final: persistent fragment-packed ww, tf32 MMA
// fj2[b,c,n,k] = f1[b,c, idx[b,n, jsel[b*4096 + c*32 + (n>>7), k]]]
__global__ __launch_bounds__(128) void k_final(
    const float* __restrict__ ww, const float* __restrict__ gw, const float* __restrict__ bw,
    const float* __restrict__ wc2, const float* __restrict__ gc2, const float* __restrict__ bc2,
    float* __restrict__ out) {
    int t = threadIdx.x;  // 128
    int wid = t >> 5, lane = t & 31, grp = lane >> 2, tig = lane & 3;

    extern __shared__ __align__(16) char dsm[];
    uint4 (*aw)           = (uint4*)(dsm + SM_AW);              // frag-packed tf32 ww: [(R*16+ks)*32 + lane]
    unsigned (*fj2t)[132] = (unsigned(*)[132])(dsm + SM_FJ2T);  // per-pair tf32 fj2
    float (*cols)[COUT]   = (float(*)[COUT])(dsm + SM_A);       // gather (phase 1)
    float (*lgt)[25]      = (float(*)[25])(dsm + SM_A);         // logits (phase 3)
    __shared__ float sdp2[2][3][KNB];
    __shared__ int   sidxn[2][KNB];

    // one-time: stage FULL ww as tf32 in FRAGMENT order.
    // aw[(R*16+ks)*32 + (grp*4+tig)] = { ww[R*16+grp][ks*8+tig], ww[R*16+8+grp][ks*8+tig],
    //                                    ww[R*16+grp][ks*8+tig+4], ww[R*16+8+grp][ks*8+tig+4] } (tf32 bits)
    {
        unsigned* aw32 = (unsigned*)aw;
        for (int e = t; e < 128 * 32; e += 128) {
            int row = e >> 5, q = e & 31;
            float4 v = __ldg((const float4*)(ww + (size_t)row * COUT + q * 4));
            int R = row >> 4, g8 = row & 7, hr = (row >> 3) & 1;
#pragma unroll
            for (int j = 0; j < 4; j++) {
                int c = q * 4 + j;
                int ks = c >> 3, tg = c & 3, hc = (c >> 2) & 1;
                float fv = (j == 0) ? v.x : (j == 1) ? v.y : (j == 2) ? v.z : v.w;
                aw32[(((R * 16 + ks) * 32) + (g8 * 4 + tg)) * 4 + (hr + 2 * hc)] = f2tf(fv);
            }
        }
    }

    // loop-invariant epilogue scalars
    float inv = rsqrtf(1.0f + 1e-5f);
    float sw = gw[t] * inv, bwv = bw[t];
    float w0 = wc2[t*3], w1v = wc2[t*3+1], w2v = wc2[t*3+2];
    float sc = gc2[t] * inv, bc = bc2[t];

    for (int pair = blockIdx.x; pair < NPAIRS; pair += FINAL_GRID) {
        int b = pair >> 11;
        int n0 = (pair & 2047) * 2;

        __syncthreads();   // prev-pair epilogue readers done; first iter: aw ready
        if (t < 2 * KNB) sidxn[t / KNB][t % KNB] = g_idx[((size_t)b * Nv + n0 + t / KNB) * KNB + (t % KNB)];
        for (int e = t; e < 2 * 72; e += 128) {
            int i = e / 72, r = e % 72;
            sdp2[i][r / KNB][r % KNB] = g_nn[(((size_t)b*3 + r / KNB) * Nv + n0 + i) * KNB + (r % KNB)];
        }
        int grow = ((b * COUT + t) * 32 + (n0 >> 7)) * KNB;
        int jidx[KNB];
        {
            const int4* jp = (const int4*)(g_jsel + grow);
#pragma unroll
            for (int q = 0; q < 6; q++) {
                int4 v = jp[q];
                jidx[4*q+0] = v.x; jidx[4*q+1] = v.y;
                jidx[4*q+2] = v.z; jidx[4*q+3] = v.w;
            }
        }

        // phase 1: gather + shuffle; keep fp32 in regs, write tf32 to smem
        float fv[2 * KNB];
#pragma unroll
        for (int i = 0; i < 2; i++) {
            __syncthreads();
            {
                int c4 = t & 31, jb = t >> 5;
#pragma unroll
                for (int r = 0; r < 6; r++) {
                    int j = r * 4 + jb;
                    ((float4*)&cols[j][0])[c4] =
                        ((const float4*)(g_f1t + ((size_t)b * Nv + sidxn[i][j]) * COUT))[c4];
                }
            }
            __syncthreads();
#pragma unroll
            for (int k = 0; k < KNB; k++) {
                float v = cols[jidx[k]][t];
                fv[i * KNB + k] = v;
                fj2t[i * KNB + k][t] = f2tf(v);
            }
        }
        __syncthreads();   // fj2t ready; cols region free (lgt may be written)

        // phase 2: MMA loop — a-frags via single LDS.128 each
        float d[2][6][4];
#pragma unroll
        for (int m = 0; m < 2; m++)
#pragma unroll
            for (int nn = 0; nn < 6; nn++)
#pragma unroll
                for (int q = 0; q < 4; q++) d[m][nn][q] = 0.f;

#pragma unroll
        for (int ks = 0; ks < 16; ks++) {
            int cc = ks * 8 + tig;
            unsigned bf[6][2];
#pragma unroll
            for (int nn = 0; nn < 6; nn++) {
                int r = nn * 8 + grp;
                bf[nn][0] = fj2t[r][cc];
                bf[nn][1] = fj2t[r][cc + 4];
            }
#pragma unroll
            for (int m = 0; m < 2; m++) {
                int R = wid * 2 + m;
                uint4 A = aw[(R * 16 + ks) * 32 + lane];
#pragma unroll
                for (int nn = 0; nn < 6; nn++)
                    mma_tf32(d[m][nn], A.x, A.y, A.z, A.w, bf[nn][0], bf[nn][1]);
            }
        }

        // phase 3: per-point spill + epilogue (warp-local lgt rows)
#pragma unroll
        for (int i = 0; i < 2; i++) {
#pragma unroll
            for (int m = 0; m < 2; m++) {
                int r0 = wid * 32 + m * 16 + grp;
#pragma unroll
                for (int nn = 0; nn < 3; nn++) {
                    int nn2 = i * 3 + nn;
                    int cc = nn * 8 + 2 * tig;
                    lgt[r0][cc]         = d[m][nn2][0];
                    lgt[r0][cc + 1]     = d[m][nn2][1];
                    lgt[r0 + 8][cc]     = d[m][nn2][2];
                    lgt[r0 + 8][cc + 1] = d[m][nn2][3];
                }
            }
            __syncwarp();

            float l[KNB];
            float mx = -3.402823e38f;
#pragma unroll
            for (int k = 0; k < KNB; k++) {
                l[k] = fmaf(lgt[t][k], sw, bwv);
                mx = fmaxf(mx, l[k]);
            }
            float sum = 0.f;
#pragma unroll
            for (int k = 0; k < KNB; k++) { float e = __expf(l[k] - mx); l[k] = e; sum += e; }
            float rs = 1.f / sum;
            float pe[KNB];
            float fo = -3.402823e38f;
#pragma unroll
            for (int k = 0; k < KNB; k++) {
                float v = w0 * sdp2[i][0][k] + w1v * sdp2[i][1][k] + w2v * sdp2[i][2][k];
                v = fmaxf(fmaf(v, sc, bc), 0.f);
                pe[k] = v;
                fo = fmaxf(fo, (v + fv[i * KNB + k]) * (l[k] * rs));
            }
            float* po = out + PE_OFF + (((size_t)b * COUT + t) * Nv + n0 + i) * KNB;
#pragma unroll
            for (int q = 0; q < 6; q++)
                ((float4*)po)[q] = make_float4(pe[4*q], pe[4*q+1], pe[4*q+2], pe[4*q+3]);
            out[FOUT_OFF + ((size_t)b * COUT + t) * Nv + n0 + i] = fo;
            __syncwarp();  // point-1 spill must not race point-0 reads
        }
    }
}

// ----------------------------------------------------------------
extern "C" void kernel_launch(void* const* d_in, const int* in_sizes, int n_in,
                              void* d_out, int out_size) {
    const float* pc  = (const float*)d_in[0];
    const float* f   = (const float*)d_in[1];
    const float* w1  = (const float*)d_in[3];
    const float* g1  = (const float*)d_in[4];
    const float* b1  = (const float*)d_in[5];
    const float* wd1 = (const float*)d_in[6];
    const float* gd1 = (const float*)d_in[7];
    const float* bd1 = (const float*)d_in[8];
    const float* wd2 = (const float*)d_in[9];
    const float* gd2 = (const float*)d_in[10];
    const float* bd2 = (const float*)d_in[11];
    const float* wd3 = (const float*)d_in[12];
    const float* gd3 = (const float*)d_in[13];
    const float* bd3 = (const float*)d_in[14];
    const float* ww  = (const float*)d_in[15];
    const float* gw  = (const float*)d_in[16];
    const float* bw  = (const float*)d_in[17];
    const float* wc2 = (const float*)d_in[18];
    const float* gc2 = (const float*)d_in[19];
    const float* bc2 = (const float*)d_in[20];
    float* out = (float*)d_out;

    static int smem_set = 0;
    if (!smem_set) {
        cudaFuncSetAttribute(k_final, cudaFuncAttributeMaxDynamicSharedMemorySize, SM_TOTAL);
        smem_set = 1;
    }

    k_f1<<<dim3(Nv / 32, Bv), 128>>>(f, w1, g1, b1);
    k_ballq<<<dim3(Nv / 32, Bv), 1024>>>(pc, out);
    k_fps<<<NSEG / 8, 256>>>();
    k_mlp<<<dim3(Nv / 8, Bv), dim3(24, 8)>>>(wd1, gd1, bd1, wd2, gd2, bd2, wd3, gd3, bd3);
    k_nnq<<<NSEG / 8, 256>>>();
    k_final<<<FINAL_GRID, 128, SM_TOTAL>>>(ww, gw, bw, wc2, gc2, bc2, out);
}

// round 16
// speedup vs baseline: 1.0958x; 1.0958x over previous
#include <cuda_runtime.h>
#include <cuda_fp16.h>
#include <math.h>

#define Bv   2
#define Nv   4096
#define CIN  64
#define COUT 128
#define KNB  24
#define R2   0.0225f

// Output layout: pc (2*4096*6) | fout (2*128*4096) | pe (2*128*4096*24)
#define PC_ELEMS   (Bv*Nv*6)
#define FOUT_OFF   (PC_ELEMS)
#define FOUT_ELEMS (Bv*COUT*Nv)
#define PE_OFF     (FOUT_OFF + FOUT_ELEMS)

#define NSEG   (Bv*Nv)
#define DPLEN  (Bv*3*Nv*KNB)

__device__ float g_f1t[Bv*Nv*COUT];   // transposed  [b][n][c]
__device__ float g_dp[DPLEN];
__device__ float g_ndp[DPLEN];
__device__ float g_nn[DPLEN];
__device__ int   g_idx[Bv*Nv*KNB];
__device__ int   g_jsel[NSEG*KNB];

__device__ __forceinline__ unsigned pack_h2(float a, float b) {
    __half2 h = __floats2half2_rn(a, b);
    return *(unsigned*)&h;
}
__device__ __forceinline__ void mma_f16(float* d, unsigned a0, unsigned a1, unsigned a2, unsigned a3,
                                        unsigned b0, unsigned b1) {
    asm volatile(
        "mma.sync.aligned.m16n8k16.row.col.f32.f16.f16.f32 "
        "{%0,%1,%2,%3}, {%4,%5,%6,%7}, {%8,%9}, {%0,%1,%2,%3};\n"
        : "+f"(d[0]), "+f"(d[1]), "+f"(d[2]), "+f"(d[3])
        : "r"(a0), "r"(a1), "r"(a2), "r"(a3), "r"(b0), "r"(b1));
}

// k_final dynamic smem layout:
//   wwh  : u32[128][68]  fp16x2 ww  = 34816 B (one-shot per block)
//   fj2h : half[48][136]            = 13056 B (per pair)
//   A-region (union): cols[24][128] f32 (12288) / lgt[128][25] f32 (12800)
#define SM_WWH   0
#define SM_FJH   34816
#define SM_A     (34816 + 13056)      // 47872
#define SM_TOTAL (SM_A + 12800)       // 60672

// ---------------------------------------------------------------- f1 = relu(bn(w1 @ f)); store transposed [b][n][c]
__global__ void k_f1(const float* __restrict__ f, const float* __restrict__ w1,
                     const float* __restrict__ g1, const float* __restrict__ b1) {
    int b = blockIdx.y;
    int col0 = blockIdx.x * 32;
    int t = threadIdx.x;
    __shared__ float fs[64][32];
    for (int e = t; e < 64 * 32; e += 128) {
        int row = e >> 5, col = e & 31;
        fs[row][col] = f[((size_t)b * CIN + row) * Nv + col0 + col];
    }
    __syncthreads();
    float acc[32];
#pragma unroll
    for (int i = 0; i < 32; i++) acc[i] = 0.f;
    const float* wr = w1 + t * CIN;
    for (int ci = 0; ci < CIN; ci++) {
        float wv = __ldg(wr + ci);
        const float4* r = (const float4*)&fs[ci][0];
#pragma unroll
        for (int q = 0; q < 8; q++) {
            float4 v = r[q];
            acc[4*q+0] = fmaf(wv, v.x, acc[4*q+0]);
            acc[4*q+1] = fmaf(wv, v.y, acc[4*q+1]);
            acc[4*q+2] = fmaf(wv, v.z, acc[4*q+2]);
            acc[4*q+3] = fmaf(wv, v.w, acc[4*q+3]);
        }
    }
    float inv = rsqrtf(1.0f + 1e-5f);
    float s = g1[t] * inv, bb = b1[t];
    float* ot = g_f1t + ((size_t)b * Nv + col0) * COUT + t;
#pragma unroll
    for (int i = 0; i < 32; i++)
        ot[(size_t)i * COUT] = fmaxf(fmaf(acc[i], s, bb), 0.f);
}

// ---------------------------------------------------------------- ball query 1: 32 queries/block; pc copy folded
__global__ __launch_bounds__(1024) void k_ballq(const float* __restrict__ pc, float* __restrict__ out) {
    __shared__ float sx[2048], sy[2048], sz[2048];
    __shared__ int   widx[32][KNB];
    __shared__ float sdp[32][3][KNB];
    int b = blockIdx.y;
    int t = threadIdx.x;
    int w = t >> 5, lane = t & 31;
    int n = blockIdx.x * 32 + w;
    const float* qp = pc + ((size_t)b * Nv + n) * 6;
    float qx = qp[0], qy = qp[1], qz = qp[2];
    float qq = qx*qx + qy*qy + qz*qz;
    int count = 0;
    for (int c = 0; c < 2; c++) {
        __syncthreads();
        for (int i = t; i < 2048; i += 1024) {
            const float* pp = pc + ((size_t)b * Nv + c * 2048 + i) * 6;
            sx[i] = pp[0]; sy[i] = pp[1]; sz[i] = pp[2];
        }
        __syncthreads();
        if (count >= KNB) continue;
        for (int base = 0; base < 2048; base += 32) {
            int s = base + lane;
            float x = sx[s], y = sy[s], z = sz[s];
            float ss = x*x + y*y + z*z;
            float d2 = qq + ss - 2.f * (qx*x + qy*y + qz*z);
            bool hit = d2 < R2;
            unsigned m = __ballot_sync(0xffffffffu, hit);
            if (hit) {
                int r = count + __popc(m & ((1u << lane) - 1u));
                if (r < KNB) {
                    widx[w][r] = c * 2048 + s;
                    sdp[w][0][r] = x - qx;
                    sdp[w][1][r] = y - qy;
                    sdp[w][2][r] = z - qz;
                }
            }
            count += __popc(m);
            if (count >= KNB) break;
        }
    }
    __syncwarp();
    int cnt = count > KNB ? KNB : count;
    if (lane < KNB) {
        int src = (lane < cnt) ? lane : 0;
        size_t gi = ((size_t)b * Nv + n) * KNB + lane;
        g_idx[gi] = widx[w][src];
        g_dp[(((size_t)b*3 + 0) * Nv + n) * KNB + lane] = sdp[w][0][src];
        g_dp[(((size_t)b*3 + 1) * Nv + n) * KNB + lane] = sdp[w][1][src];
        g_dp[(((size_t)b*3 + 2) * Nv + n) * KNB + lane] = sdp[w][2][src];
    }
    if (blockIdx.x == 0) {
        const float* src = pc + (size_t)b * Nv * 6;
        float* dst = out + (size_t)b * Nv * 6;
        for (int i = t; i < Nv * 6; i += 1024) dst[i] = src[i];
    }
}

// ---------------------------------------------------------------- FPS on flat 72-float segments (REDUX argmax)
__global__ void k_fps() {
    int t = threadIdx.x, w = t >> 5, lane = t & 31;
    int g = blockIdx.x * 8 + w;
    __shared__ float sp[8][KNB][3];
    __shared__ int   sperm[8][KNB];
    const float* seg = g_dp + (size_t)g * 72;
    if (lane < KNB) {
        sp[w][lane][0] = seg[lane*3];
        sp[w][lane][1] = seg[lane*3+1];
        sp[w][lane][2] = seg[lane*3+2];
    }
    __syncwarp();
    float px = 0.f, py = 0.f, pz = 0.f, dist = 1e10f;
    if (lane < KNB) { px = sp[w][lane][0]; py = sp[w][lane][1]; pz = sp[w][lane][2]; }
    int last = 0;
    if (lane == 0) sperm[w][0] = 0;
    for (int i = 1; i < KNB; i++) {
        float lx = __shfl_sync(0xffffffffu, px, last);
        float ly = __shfl_sync(0xffffffffu, py, last);
        float lz = __shfl_sync(0xffffffffu, pz, last);
        float dx = px - lx, dy = py - ly, dz = pz - lz;
        float d = dx*dx + dy*dy + dz*dz;
        if (lane < KNB) dist = fminf(dist, d);
        unsigned key = (lane < KNB) ? __float_as_uint(dist) : 0u;
        unsigned mv = __reduce_max_sync(0xffffffffu, key);
        unsigned elig = __ballot_sync(0xffffffffu, key == mv);
        last = __ffs(elig) - 1;
        if (lane == 0) sperm[w][i] = last;
    }
    __syncwarp();
    float* o = g_ndp + (size_t)g * 72;
    if (lane < KNB) {
        int s = sperm[w][lane];
        o[lane*3]   = sp[w][s][0];
        o[lane*3+1] = sp[w][s][1];
        o[lane*3+2] = sp[w][s][2];
    }
}

// ---------------------------------------------------------------- delta MLP (3->32->16->3); block (24,8): k=tx, no divides
__global__ __launch_bounds__(192) void k_mlp(
    const float* __restrict__ wd1, const float* __restrict__ gd1, const float* __restrict__ bd1,
    const float* __restrict__ wd2, const float* __restrict__ gd2, const float* __restrict__ bd2,
    const float* __restrict__ wd3, const float* __restrict__ gd3, const float* __restrict__ bd3) {
    __shared__ float s_wd1[96], s_a1[32], s_b1[32];
    __shared__ float s_wd2[512], s_a2[16], s_b2[16];
    __shared__ float s_wd3[48], s_a3[3], s_b3[3];
    int tid = threadIdx.y * 24 + threadIdx.x;
    float inv = rsqrtf(1.0f + 1e-5f);
    if (tid < 96) s_wd1[tid] = wd1[tid];
    if (tid < 32) { s_a1[tid] = gd1[tid] * inv; s_b1[tid] = bd1[tid]; }
    for (int i = tid; i < 512; i += 192) s_wd2[i] = wd2[i];
    if (tid < 16) { s_a2[tid] = gd2[tid] * inv; s_b2[tid] = bd2[tid]; }
    if (tid >= 96 && tid < 144) s_wd3[tid-96] = wd3[tid-96];
    if (tid >= 144 && tid < 147) { s_a3[tid-144] = gd3[tid-144] * inv; s_b3[tid-144] = bd3[tid-144]; }
    __syncthreads();
    int k = threadIdx.x;
    int n = blockIdx.x * 8 + threadIdx.y;
    int b = blockIdx.y;
    size_t base = (((size_t)b * 3) * Nv + n) * KNB + k;
    const size_t CS = (size_t)Nv * KNB;
    float x0 = g_ndp[base], x1 = g_ndp[base + CS], x2 = g_ndp[base + 2*CS];
    float h2[16];
#pragma unroll
    for (int o = 0; o < 16; o++) h2[o] = 0.f;
#pragma unroll
    for (int c1 = 0; c1 < 32; c1++) {
        float a = s_wd1[c1*3]*x0 + s_wd1[c1*3+1]*x1 + s_wd1[c1*3+2]*x2;
        float h1v = fmaxf(fmaf(a, s_a1[c1], s_b1[c1]), 0.f);
#pragma unroll
        for (int o = 0; o < 16; o++)
            h2[o] = fmaf(s_wd2[o*32+c1], h1v, h2[o]);
    }
#pragma unroll
    for (int o = 0; o < 16; o++)
        h2[o] = fmaxf(fmaf(h2[o], s_a2[o], s_b2[o]), 0.f);
#pragma unroll
    for (int c = 0; c < 3; c++) {
        float a = 0.f;
#pragma unroll
        for (int ci = 0; ci < 16; ci++) a = fmaf(s_wd3[c*16+ci], h2[ci], a);
        float d = fmaf(a, s_a3[c], s_b3[c]);
        float xin = (c == 0) ? x0 : (c == 1) ? x1 : x2;
        g_ndp[base + (size_t)c * CS] = xin + d;
    }
}

// ---------------------------------------------------------------- NN query (k=1) on flat segments: q=new_dp, s=dp
__global__ void k_nnq() {
    int t = threadIdx.x, w = t >> 5, lane = t & 31;
    int g = blockIdx.x * 8 + w;
    __shared__ float sp[8][KNB][3];
    __shared__ float sss[8][KNB];
    const float* sseg = g_dp + (size_t)g * 72;
    if (lane < KNB) {
        float x = sseg[lane*3], y = sseg[lane*3+1], z = sseg[lane*3+2];
        sp[w][lane][0] = x; sp[w][lane][1] = y; sp[w][lane][2] = z;
        sss[w][lane] = x*x + y*y + z*z;
    }
    __syncwarp();
    if (lane < KNB) {
        const float* qseg = g_ndp + (size_t)g * 72;
        float qx = qseg[lane*3], qy = qseg[lane*3+1], qz = qseg[lane*3+2];
        float qq = qx*qx + qy*qy + qz*qz;
        int found = -1;
        for (int jj = 0; jj < KNB; jj++) {
            float d2 = qq + sss[w][jj] - 2.f * (qx*sp[w][jj][0] + qy*sp[w][jj][1] + qz*sp[w][jj][2]);
            if (d2 < R2) { found = jj; break; }
        }
        int j = found < 0 ? 0 : found;
        g_jsel[g * KNB + lane] = j;
        float* o = g_nn + (size_t)g * 72;
        o[0*KNB + lane] = sp[w][j][0] - qx;
        o[1*KNB + lane] = sp[w][j][1] - qy;
        o[2*KNB + lane] = sp[w][j][2] - qz;
    }
}

// ---------------------------------------------------------------- fused final: 2 points/block, fp16 MMA (m16n8k16)
// fj2[b,c,n,k] = f1[b,c, idx[b,n, jsel[b*4096 + c*32 + (n>>7), k]]]
__global__ __launch_bounds__(128) void k_final(
    const float* __restrict__ ww, const float* __restrict__ gw, const float* __restrict__ bw,
    const float* __restrict__ wc2, const float* __restrict__ gc2, const float* __restrict__ bc2,
    float* __restrict__ out) {
    int n0 = blockIdx.x * 2, b = blockIdx.y;
    int t = threadIdx.x;
    int wid = t >> 5, lane = t & 31, grp = lane >> 2, tig = lane & 3;

    extern __shared__ __align__(16) char dsm[];
    unsigned* wwh       = (unsigned*)(dsm + SM_WWH);     // [128][68] u32: fp16x2 ww
    __half*   fjh       = (__half*)(dsm + SM_FJH);       // [48][136] halves
    float (*cols)[COUT] = (float(*)[COUT])(dsm + SM_A);  // phase 1
    float (*lgt)[25]    = (float(*)[25])(dsm + SM_A);    // phase 3
    __shared__ float sdp2[2][3][KNB];
    __shared__ int   sidxn[2][KNB];

    // one-shot: ww -> fp16x2 (rows 128, ALL 32 float4 per row -> 64 u32 cols, stride 68)
    for (int e = t; e < 128 * 32; e += 128) {
        int row = e >> 5, qf = e & 31;
        float4 v = __ldg((const float4*)(ww + (size_t)row * COUT + qf * 4));
        wwh[row * 68 + qf * 2]     = pack_h2(v.x, v.y);
        wwh[row * 68 + qf * 2 + 1] = pack_h2(v.z, v.w);
    }

    int grow = ((b * COUT + t) * 32 + (n0 >> 7)) * KNB;
    int jidx[KNB];
    {
        const int4* jp = (const int4*)(g_jsel + grow);
#pragma unroll
        for (int q = 0; q < 6; q++) {
            int4 v = jp[q];
            jidx[4*q+0] = v.x; jidx[4*q+1] = v.y;
            jidx[4*q+2] = v.z; jidx[4*q+3] = v.w;
        }
    }
    if (t < 2 * KNB) sidxn[t / KNB][t % KNB] = g_idx[((size_t)b * Nv + n0 + t / KNB) * KNB + (t % KNB)];
    for (int e = t; e < 2 * 72; e += 128) {
        int i = e / 72, r = e % 72;
        sdp2[i][r / KNB][r % KNB] = g_nn[(((size_t)b*3 + r / KNB) * Nv + n0 + i) * KNB + (r % KNB)];
    }

    // phase 1: gather + shuffle; fp32 in regs (fv), fp16 to smem
    float fv[2 * KNB];
#pragma unroll
    for (int i = 0; i < 2; i++) {
        __syncthreads();
        {
            int c4 = t & 31, jb = t >> 5;
#pragma unroll
            for (int r = 0; r < 6; r++) {
                int j = r * 4 + jb;
                ((float4*)&cols[j][0])[c4] =
                    ((const float4*)(g_f1t + ((size_t)b * Nv + sidxn[i][j]) * COUT))[c4];
            }
        }
        __syncthreads();
#pragma unroll
        for (int k = 0; k < KNB; k++) {
            float v = cols[jidx[k]][t];
            fv[i * KNB + k] = v;
            fjh[(i * KNB + k) * 136 + t] = __float2half_rn(v);
        }
    }
    __syncthreads();   // fjh + wwh ready; cols region free (lgt may be written)

    // phase 2: fp16 MMA — D[o, r] = sum_c ww[o,c] * fj2[r][c], r in [0,48)
    float d[2][6][4];
#pragma unroll
    for (int m = 0; m < 2; m++)
#pragma unroll
        for (int nn = 0; nn < 6; nn++)
#pragma unroll
            for (int q = 0; q < 4; q++) d[m][nn][q] = 0.f;

#pragma unroll
    for (int ks = 0; ks < 8; ks++) {
        int cc = ks * 8 + tig;              // u32 column
        unsigned bf[6][2];
#pragma unroll
        for (int nn = 0; nn < 6; nn++) {
            int r = nn * 8 + grp;
            const unsigned* br = (const unsigned*)(fjh + r * 136);
            bf[nn][0] = br[cc];
            bf[nn][1] = br[cc + 4];
        }
#pragma unroll
        for (int m = 0; m < 2; m++) {
            int o = wid * 32 + m * 16;
            unsigned a0 = wwh[(o + grp) * 68 + cc];
            unsigned a1 = wwh[(o + 8 + grp) * 68 + cc];
            unsigned a2 = wwh[(o + grp) * 68 + cc + 4];
            unsigned a3 = wwh[(o + 8 + grp) * 68 + cc + 4];
#pragma unroll
            for (int nn = 0; nn < 6; nn++)
                mma_f16(d[m][nn], a0, a1, a2, a3, bf[nn][0], bf[nn][1]);
        }
    }

    // phase 3: per-point spill + epilogue (warp-local lgt rows)
    float inv = rsqrtf(1.0f + 1e-5f);
    float sw = gw[t] * inv, bwv = bw[t];
    float w0 = wc2[t*3], w1v = wc2[t*3+1], w2v = wc2[t*3+2];
    float sc = gc2[t] * inv, bc = bc2[t];

#pragma unroll
    for (int i = 0; i < 2; i++) {
#pragma unroll
        for (int m = 0; m < 2; m++) {
            int r0 = wid * 32 + m * 16 + grp;
#pragma unroll
            for (int nn = 0; nn < 3; nn++) {
                int nn2 = i * 3 + nn;
                int cc = nn * 8 + 2 * tig;
                lgt[r0][cc]         = d[m][nn2][0];
                lgt[r0][cc + 1]     = d[m][nn2][1];
                lgt[r0 + 8][cc]     = d[m][nn2][2];
                lgt[r0 + 8][cc + 1] = d[m][nn2][3];
            }
        }
        __syncwarp();

        float l[KNB];
        float mx = -3.402823e38f;
#pragma unroll
        for (int k = 0; k < KNB; k++) {
            l[k] = fmaf(lgt[t][k], sw, bwv);
            mx = fmaxf(mx, l[k]);
        }
        float sum = 0.f;
#pragma unroll
        for (int k = 0; k < KNB; k++) { float e = __expf(l[k] - mx); l[k] = e; sum += e; }
        float rs = 1.f / sum;
        float pe[KNB];
        float fo = -3.402823e38f;
#pragma unroll
        for (int k = 0; k < KNB; k++) {
            float v = w0 * sdp2[i][0][k] + w1v * sdp2[i][1][k] + w2v * sdp2[i][2][k];
            v = fmaxf(fmaf(v, sc, bc), 0.f);
            pe[k] = v;
            fo = fmaxf(fo, (v + fv[i * KNB + k]) * (l[k] * rs));
        }
        float* po = out + PE_OFF + (((size_t)b * COUT + t) * Nv + n0 + i) * KNB;
#pragma unroll
        for (int q = 0; q < 6; q++)
            ((float4*)po)[q] = make_float4(pe[4*q], pe[4*q+1], pe[4*q+2], pe[4*q+3]);
        out[FOUT_OFF + ((size_t)b * COUT + t) * Nv + n0 + i] = fo;
        __syncwarp();
    }
}

// ----------------------------------------------------------------
extern "C" void kernel_launch(void* const* d_in, const int* in_sizes, int n_in,
                              void* d_out, int out_size) {
    const float* pc  = (const float*)d_in[0];
    const float* f   = (const float*)d_in[1];
    const float* w1  = (const float*)d_in[3];
    const float* g1  = (const float*)d_in[4];
    const float* b1  = (const float*)d_in[5];
    const float* wd1 = (const float*)d_in[6];
    const float* gd1 = (const float*)d_in[7];
    const float* bd1 = (const float*)d_in[8];
    const float* wd2 = (const float*)d_in[9];
    const float* gd2 = (const float*)d_in[10];
    const float* bd2 = (const float*)d_in[11];
    const float* wd3 = (const float*)d_in[12];
    const float* gd3 = (const float*)d_in[13];
    const float* bd3 = (const float*)d_in[14];
    const float* ww  = (const float*)d_in[15];
    const float* gw  = (const float*)d_in[16];
    const float* bw  = (const float*)d_in[17];
    const float* wc2 = (const float*)d_in[18];
    const float* gc2 = (const float*)d_in[19];
    const float* bc2 = (const float*)d_in[20];
    float* out = (float*)d_out;

    static int smem_set = 0;
    if (!smem_set) {
        cudaFuncSetAttribute(k_final, cudaFuncAttributeMaxDynamicSharedMemorySize, SM_TOTAL);
        smem_set = 1;
    }

    k_f1<<<dim3(Nv / 32, Bv), 128>>>(f, w1, g1, b1);
    k_ballq<<<dim3(Nv / 32, Bv), 1024>>>(pc, out);
    k_fps<<<NSEG / 8, 256>>>();
    k_mlp<<<dim3(Nv / 8, Bv), dim3(24, 8)>>>(wd1, gd1, bd1, wd2, gd2, bd2, wd3, gd3, bd3);
    k_nnq<<<NSEG / 8, 256>>>();
    k_final<<<dim3(Nv / 2, Bv), 128, SM_TOTAL>>>(ww, gw, bw, wc2, gc2, bc2, out);
}